// round 1
// baseline (speedup 1.0000x reference)
#include <cuda_runtime.h>
#include <math.h>
#include <stdint.h>

// Problem constants (fixed shapes from reference)
#define N_TOK 65536   // B*T = 8*8192
#define HDIM  512
#define NEXP  4
#define RNK   16

// ---------------- device scratch (no allocations allowed) ----------------
__device__ float g_w[N_TOK * NEXP];          // normalized gate weights  [N,4]   (1 MB)
__device__ float g_wz[N_TOK * NEXP * RNK];   // w * z (rank-16 codes)    [N,64]  (16 MB)
__device__ float g_C[NEXP * RNK * HDIM];     // C[e] = lora_B[e] @ fc2_w[e]^T  (128 KB)

// =========================================================================
// Kernel 1: C[e][r][d] = sum_o lora_B[e][r][o] * fc2_w[e][d][o]
// grid (E, H/64), 256 threads
// =========================================================================
__global__ void precompute_C_kernel(const float* __restrict__ lora_B,
                                    const float* __restrict__ fc2_w) {
    const int e = blockIdx.x;
    const int dbase = blockIdx.y * 64;
    __shared__ float lbs[RNK * HDIM];  // 32 KB, lora_B[e] fully resident
    for (int i = threadIdx.x; i < RNK * HDIM; i += blockDim.x)
        lbs[i] = lora_B[(size_t)e * RNK * HDIM + i];
    __syncthreads();

    const int warp = threadIdx.x >> 5, lane = threadIdx.x & 31;
    for (int dd = 0; dd < 8; dd++) {
        const int d = dbase + warp * 8 + dd;
        float acc[RNK];
#pragma unroll
        for (int r = 0; r < RNK; r++) acc[r] = 0.f;
        const float* fr = fc2_w + ((size_t)e * HDIM + d) * HDIM;
        for (int o = lane; o < HDIM; o += 32) {
            float fv = fr[o];
#pragma unroll
            for (int r = 0; r < RNK; r++) acc[r] += fv * lbs[r * HDIM + o];
        }
#pragma unroll
        for (int r = 0; r < RNK; r++) {
#pragma unroll
            for (int off = 16; off > 0; off >>= 1)
                acc[r] += __shfl_xor_sync(0xffffffffu, acc[r], off);
        }
        if (lane == 0) {
#pragma unroll
            for (int r = 0; r < RNK; r++)
                g_C[(size_t)(e * RNK + r) * HDIM + d] = acc[r];
        }
    }
}

// =========================================================================
// Kernel 2: gating.  One warp per token; fp32 throughout to match reference
// selection boundaries.  grid N/8, 256 threads.
// =========================================================================
__global__ void gating_kernel(const float* __restrict__ x,
                              const float* __restrict__ gate_w,
                              const float* __restrict__ thr_w) {
    const int warp = threadIdx.x >> 5, lane = threadIdx.x & 31;
    const int n = blockIdx.x * 8 + warp;
    const float* xr = x + (size_t)n * HDIM;

    float a0 = 0.f, a1 = 0.f, a2 = 0.f, a3 = 0.f, at = 0.f;
    for (int k = lane; k < HDIM; k += 32) {
        float xv = xr[k];
        a0 += xv * gate_w[0 * HDIM + k];
        a1 += xv * gate_w[1 * HDIM + k];
        a2 += xv * gate_w[2 * HDIM + k];
        a3 += xv * gate_w[3 * HDIM + k];
        at += xv * thr_w[k];
    }
#pragma unroll
    for (int off = 16; off > 0; off >>= 1) {
        a0 += __shfl_xor_sync(0xffffffffu, a0, off);
        a1 += __shfl_xor_sync(0xffffffffu, a1, off);
        a2 += __shfl_xor_sync(0xffffffffu, a2, off);
        a3 += __shfl_xor_sync(0xffffffffu, a3, off);
        at += __shfl_xor_sync(0xffffffffu, at, off);
    }
    if (lane == 0) {
        float m = fmaxf(fmaxf(a0, a1), fmaxf(a2, a3));
        float e0 = expf(a0 - m), e1 = expf(a1 - m), e2 = expf(a2 - m), e3 = expf(a3 - m);
        float inv_s = 1.f / (e0 + e1 + e2 + e3);
        float thr = (1.f / (1.f + expf(-at))) * 0.25f;
        float w0 = e0 * inv_s - thr;
        float w1 = e1 * inv_s - thr;
        float w2 = e2 * inv_s - thr;
        float w3 = e3 * inv_s - thr;
        w0 = (w0 >= 0.f) ? w0 : 0.f;
        w1 = (w1 >= 0.f) ? w1 : 0.f;
        w2 = (w2 >= 0.f) ? w2 : 0.f;
        w3 = (w3 >= 0.f) ? w3 : 0.f;
        float ws = w0 + w1 + w2 + w3;
        if (ws == 0.f) ws = 1.f;
        float inv = 1.f / ws;
        g_w[n * 4 + 0] = w0 * inv;
        g_w[n * 4 + 1] = w1 * inv;
        g_w[n * 4 + 2] = w2 * inv;
        g_w[n * 4 + 3] = w3 * inv;
    }
}

// =========================================================================
// Kernel 3: expert kernel.
//   Per block: 64 tokens x 1 expert.
//   hidden_chunk[64,64] = relu( X[64,512] @ fc1_w[e][nchunk,:]^T )  via
//   mma.sync m16n8k8 tf32; immediately projected through lora_A into
//   z[64,16] register accumulators (hidden never leaves the block).
//   Output: g_wz[n][e*16+r] = g_w[n][e] * z[n][r].
// =========================================================================
#define XS_STRIDE 516   // 512 + 4 pad (bank spread)
#define WS_STRIDE 36    // 32 + 4 pad
#define HS_STRIDE 68    // 64 + 4 pad
#define AS_STRIDE 68    // 64 + 4 pad  (transposed lora_A chunk: [16][64])

// dynamic smem: Xs(u32) + Ws(u32) + Hs(f32) + Ast(f32)
#define SMEM_EXPERT ((64 * XS_STRIDE + 64 * WS_STRIDE) * 4 + (64 * HS_STRIDE) * 4 + (RNK * AS_STRIDE) * 4)

__device__ __forceinline__ uint32_t f32_to_tf32(float v) {
    uint32_t t;
    asm("cvt.rna.tf32.f32 %0, %1;" : "=r"(t) : "f"(v));
    return t;
}

__device__ __forceinline__ void mma_tf32(float c[4], const uint32_t a[4], const uint32_t b[2]) {
    asm volatile(
        "mma.sync.aligned.m16n8k8.row.col.f32.tf32.tf32.f32 "
        "{%0,%1,%2,%3}, {%4,%5,%6,%7}, {%8,%9}, {%0,%1,%2,%3};\n"
        : "+f"(c[0]), "+f"(c[1]), "+f"(c[2]), "+f"(c[3])
        : "r"(a[0]), "r"(a[1]), "r"(a[2]), "r"(a[3]), "r"(b[0]), "r"(b[1]));
}

__global__ void __launch_bounds__(256, 1)
expert_kernel(const float* __restrict__ x,
              const float* __restrict__ fc1_w,
              const float* __restrict__ lora_A) {
    const int e    = blockIdx.x;
    const int tile = blockIdx.y;
    const int tid  = threadIdx.x;
    const int warp = tid >> 5, lane = tid & 31;
    const int g = lane >> 2, tg = lane & 3;       // mma groupID / threadID-in-group
    const int warp_m = warp >> 2, warp_n = warp & 3;

    extern __shared__ char smem_raw[];
    uint32_t* Xs  = (uint32_t*)smem_raw;                 // [64][XS_STRIDE] tf32
    uint32_t* Ws  = Xs + 64 * XS_STRIDE;                 // [64][WS_STRIDE] tf32
    float*    Hs  = (float*)(Ws + 64 * WS_STRIDE);       // [64][HS_STRIDE]
    float*    Ast = Hs + 64 * HS_STRIDE;                 // [16][AS_STRIDE]

    // ---- load X tile [64,512], round to tf32 (vectorized) ----
    const float* xt = x + (size_t)tile * 64 * HDIM;
    for (int i4 = tid; i4 < 64 * (HDIM / 4); i4 += 256) {
        int row = i4 >> 7, k4 = i4 & 127;
        float4 v = *(const float4*)&xt[(size_t)row * HDIM + k4 * 4];
        uint32_t* dst = &Xs[row * XS_STRIDE + k4 * 4];
        dst[0] = f32_to_tf32(v.x);
        dst[1] = f32_to_tf32(v.y);
        dst[2] = f32_to_tf32(v.z);
        dst[3] = f32_to_tf32(v.w);
    }
    __syncthreads();

    float zacc[4] = {0.f, 0.f, 0.f, 0.f};
    const int zr = tid & 15;        // r index (0..15)
    const int zrow0 = tid >> 4;     // base row (0..15); rows = zrow0 + 16*rr

    const float* W = fc1_w + (size_t)e * HDIM * HDIM;
    const float* A = lora_A + (size_t)e * HDIM * RNK;

    for (int nb = 0; nb < 8; nb++) {
        const int nbase = nb * 64;
        __syncthreads();  // protect Ast/Hs reuse across iterations

        // load lora_A chunk transposed: Ast[r][j] = A[nbase+j][r]
        for (int i = tid; i < 64 * RNK; i += 256) {
            int r = i >> 6, j = i & 63;
            Ast[r * AS_STRIDE + j] = A[(size_t)(nbase + j) * RNK + r];
        }

        float acc[2][2][4];
#pragma unroll
        for (int mi = 0; mi < 2; mi++)
#pragma unroll
            for (int ni = 0; ni < 2; ni++)
#pragma unroll
                for (int c = 0; c < 4; c++) acc[mi][ni][c] = 0.f;

        for (int kc = 0; kc < 16; kc++) {
            __syncthreads();  // previous mma reads of Ws complete
            // load fc1 weight chunk Ws[64][32] (vectorized), round to tf32
            for (int i4 = tid; i4 < 64 * 8; i4 += 256) {
                int nn = i4 >> 3, k4 = i4 & 7;
                float4 v = *(const float4*)&W[(size_t)(nbase + nn) * HDIM + kc * 32 + k4 * 4];
                uint32_t* dst = &Ws[nn * WS_STRIDE + k4 * 4];
                dst[0] = f32_to_tf32(v.x);
                dst[1] = f32_to_tf32(v.y);
                dst[2] = f32_to_tf32(v.z);
                dst[3] = f32_to_tf32(v.w);
            }
            __syncthreads();

#pragma unroll
            for (int s = 0; s < 4; s++) {
                const int kk = kc * 32 + s * 8;  // global k for Xs
                const int kl = s * 8;            // local k for Ws
                uint32_t a[2][4], b[2][2];
#pragma unroll
                for (int mi = 0; mi < 2; mi++) {
                    const int row = warp_m * 32 + mi * 16 + g;
                    a[mi][0] = Xs[row * XS_STRIDE + kk + tg];
                    a[mi][1] = Xs[(row + 8) * XS_STRIDE + kk + tg];
                    a[mi][2] = Xs[row * XS_STRIDE + kk + tg + 4];
                    a[mi][3] = Xs[(row + 8) * XS_STRIDE + kk + tg + 4];
                }
#pragma unroll
                for (int ni = 0; ni < 2; ni++) {
                    const int col = warp_n * 16 + ni * 8 + g;
                    b[ni][0] = Ws[col * WS_STRIDE + kl + tg];
                    b[ni][1] = Ws[col * WS_STRIDE + kl + tg + 4];
                }
#pragma unroll
                for (int mi = 0; mi < 2; mi++)
#pragma unroll
                    for (int ni = 0; ni < 2; ni++)
                        mma_tf32(acc[mi][ni], a[mi], b[ni]);
            }
        }

        __syncthreads();
        // relu + stage hidden chunk to SMEM
#pragma unroll
        for (int mi = 0; mi < 2; mi++)
#pragma unroll
            for (int ni = 0; ni < 2; ni++) {
                const int row = warp_m * 32 + mi * 16 + g;
                const int col = warp_n * 16 + ni * 8 + 2 * tg;
                Hs[row * HS_STRIDE + col]           = fmaxf(acc[mi][ni][0], 0.f);
                Hs[row * HS_STRIDE + col + 1]       = fmaxf(acc[mi][ni][1], 0.f);
                Hs[(row + 8) * HS_STRIDE + col]     = fmaxf(acc[mi][ni][2], 0.f);
                Hs[(row + 8) * HS_STRIDE + col + 1] = fmaxf(acc[mi][ni][3], 0.f);
            }
        __syncthreads();

        // z[row][r] += Hs[row][:] . Ast[r][:]   (fp32, vectorized over j)
#pragma unroll
        for (int j4 = 0; j4 < 16; j4++) {
            float4 av = *(const float4*)&Ast[zr * AS_STRIDE + j4 * 4];
#pragma unroll
            for (int rr = 0; rr < 4; rr++) {
                const int row = zrow0 + rr * 16;
                float4 hv = *(const float4*)&Hs[row * HS_STRIDE + j4 * 4];
                zacc[rr] += hv.x * av.x + hv.y * av.y + hv.z * av.z + hv.w * av.w;
            }
        }
    }

    // write w*z to scratch
#pragma unroll
    for (int rr = 0; rr < 4; rr++) {
        const int row = zrow0 + rr * 16;
        const int n = tile * 64 + row;
        const float w = g_w[n * 4 + e];
        g_wz[(size_t)n * (NEXP * RNK) + e * RNK + zr] = w * zacc[rr];
    }
}

// =========================================================================
// Kernel 4: combine.  out[n][d] = sum_{j=0..63} wz[n][j] * C[j][d]
//   C resident in SMEM (128 KB). FFMA register-tiled: each thread holds
//   4 rows x 16 d accumulators -> 4:1 FFMA:LDS.
// =========================================================================
#define SMEM_COMBINE ((64 * HDIM + 64 * 68) * 4)

__global__ void __launch_bounds__(256, 1)
combine_kernel(float* __restrict__ out) {
    extern __shared__ float csmem[];
    float* Cs = csmem;               // [64][512]
    float* Zs = Cs + 64 * HDIM;      // [64][68]

    const int tile = blockIdx.x, tid = threadIdx.x;
    for (int i = tid; i < 64 * HDIM; i += 256) Cs[i] = g_C[i];
    const float* wz = g_wz + (size_t)tile * 64 * 64;
    for (int i = tid; i < 64 * 64; i += 256) {
        int row = i >> 6, j = i & 63;
        Zs[row * 68 + j] = wz[i];
    }
    __syncthreads();

    const int warp = tid >> 5, lane = tid & 31;
    const int rowbase = warp * 8;
    float* outt = out + (size_t)tile * 64 * HDIM;

    for (int rg = 0; rg < 2; rg++) {
        float acc[4][16];
#pragma unroll
        for (int rr = 0; rr < 4; rr++)
#pragma unroll
            for (int i = 0; i < 16; i++) acc[rr][i] = 0.f;

        for (int j = 0; j < 64; j++) {
            float4 c0 = *(const float4*)&Cs[j * HDIM + 0 * 128 + lane * 4];
            float4 c1 = *(const float4*)&Cs[j * HDIM + 1 * 128 + lane * 4];
            float4 c2 = *(const float4*)&Cs[j * HDIM + 2 * 128 + lane * 4];
            float4 c3 = *(const float4*)&Cs[j * HDIM + 3 * 128 + lane * 4];
#pragma unroll
            for (int rr = 0; rr < 4; rr++) {
                const float zv = Zs[(rowbase + rg * 4 + rr) * 68 + j];
                acc[rr][0]  += zv * c0.x;  acc[rr][1]  += zv * c0.y;
                acc[rr][2]  += zv * c0.z;  acc[rr][3]  += zv * c0.w;
                acc[rr][4]  += zv * c1.x;  acc[rr][5]  += zv * c1.y;
                acc[rr][6]  += zv * c1.z;  acc[rr][7]  += zv * c1.w;
                acc[rr][8]  += zv * c2.x;  acc[rr][9]  += zv * c2.y;
                acc[rr][10] += zv * c2.z;  acc[rr][11] += zv * c2.w;
                acc[rr][12] += zv * c3.x;  acc[rr][13] += zv * c3.y;
                acc[rr][14] += zv * c3.z;  acc[rr][15] += zv * c3.w;
            }
        }
#pragma unroll
        for (int rr = 0; rr < 4; rr++) {
            const int row = rowbase + rg * 4 + rr;
#pragma unroll
            for (int i = 0; i < 4; i++) {
                float4 v = make_float4(acc[rr][i * 4 + 0], acc[rr][i * 4 + 1],
                                       acc[rr][i * 4 + 2], acc[rr][i * 4 + 3]);
                *(float4*)&outt[(size_t)row * HDIM + i * 128 + lane * 4] = v;
            }
        }
    }
}

// =========================================================================
// kernel_launch: 4 sequential launches on the default stream.
// Graph-capturable: no sync, no alloc, no memcpy.
// =========================================================================
extern "C" void kernel_launch(void* const* d_in, const int* in_sizes, int n_in,
                              void* d_out, int out_size) {
    const float* x      = (const float*)d_in[0];
    const float* gate_w = (const float*)d_in[1];
    const float* thr_w  = (const float*)d_in[2];
    const float* fc1_w  = (const float*)d_in[3];
    const float* lora_A = (const float*)d_in[4];
    const float* lora_B = (const float*)d_in[5];
    const float* fc2_w  = (const float*)d_in[6];
    float* out = (float*)d_out;

    cudaFuncSetAttribute(expert_kernel,
                         cudaFuncAttributeMaxDynamicSharedMemorySize, SMEM_EXPERT);
    cudaFuncSetAttribute(combine_kernel,
                         cudaFuncAttributeMaxDynamicSharedMemorySize, SMEM_COMBINE);

    precompute_C_kernel<<<dim3(NEXP, HDIM / 64), 256>>>(lora_B, fc2_w);
    gating_kernel<<<N_TOK / 8, 256>>>(x, gate_w, thr_w);
    expert_kernel<<<dim3(NEXP, N_TOK / 64), 256, SMEM_EXPERT>>>(x, fc1_w, lora_A);
    combine_kernel<<<N_TOK / 64, 256, SMEM_COMBINE>>>(out);
}

// round 5
// speedup vs baseline: 2.4931x; 2.4931x over previous
#include <cuda_runtime.h>
#include <math.h>
#include <stdint.h>

// Problem constants (fixed shapes)
#define N_TOK 65536   // B*T
#define HDIM  512
#define NEXP  4
#define RNK   16
#define NTILES (N_TOK / 128)   // 512 token tiles of 128

// ---------------- device scratch (static; no allocations) ----------------
__device__ float g_w[N_TOK * NEXP];                  // gate weights [N,4]
__device__ float g_wz[N_TOK * NEXP * RNK];           // w*z codes    [N,64]
__device__ float g_C[NEXP * RNK * HDIM];             // fused lora_B@fc2^T
__device__ float g_xr[N_TOK * HDIM];                 // tf32-rounded x (128MB)
__device__ float g_wr[NEXP * HDIM * HDIM];           // tf32-rounded fc1_w (4MB)

// ===================== helpers =====================
__device__ __forceinline__ uint32_t smem_to_u32(const void* p) {
    uint32_t a;
    asm("{ .reg .u64 t; cvta.to.shared.u64 t, %1; cvt.u32.u64 %0, t; }"
        : "=r"(a) : "l"(p));
    return a;
}
__device__ __forceinline__ void cp16(uint32_t dst, const float* src) {
    asm volatile("cp.async.cg.shared.global [%0], [%1], 16;" :: "r"(dst), "l"(src));
}
__device__ __forceinline__ uint32_t tf32_rna(float v) {
    uint32_t t;
    asm("cvt.rna.tf32.f32 %0, %1;" : "=r"(t) : "f"(v));
    return t;
}
__device__ __forceinline__ void mma_tf32(float c[4], const uint32_t a[4], const uint32_t b[2]) {
    asm volatile(
        "mma.sync.aligned.m16n8k8.row.col.f32.tf32.tf32.f32 "
        "{%0,%1,%2,%3}, {%4,%5,%6,%7}, {%8,%9}, {%0,%1,%2,%3};\n"
        : "+f"(c[0]), "+f"(c[1]), "+f"(c[2]), "+f"(c[3])
        : "r"(a[0]), "r"(a[1]), "r"(a[2]), "r"(a[3]), "r"(b[0]), "r"(b[1]));
}

// =========================================================================
// Kernel 0a/0b: round inputs to tf32 (rna) into scratch
// =========================================================================
__global__ void round_x_kernel(const float4* __restrict__ src) {
    int i = blockIdx.x * blockDim.x + threadIdx.x;
    float4 v = src[i];
    uint4 o;
    o.x = tf32_rna(v.x); o.y = tf32_rna(v.y); o.z = tf32_rna(v.z); o.w = tf32_rna(v.w);
    ((uint4*)g_xr)[i] = o;
}
__global__ void round_w_kernel(const float4* __restrict__ src) {
    int i = blockIdx.x * blockDim.x + threadIdx.x;
    float4 v = src[i];
    uint4 o;
    o.x = tf32_rna(v.x); o.y = tf32_rna(v.y); o.z = tf32_rna(v.z); o.w = tf32_rna(v.w);
    ((uint4*)g_wr)[i] = o;
}

// =========================================================================
// Kernel 1: C[e][r][d] = sum_o lora_B[e][r][o] * fc2_w[e][d][o]
// =========================================================================
__global__ void precompute_C_kernel(const float* __restrict__ lora_B,
                                    const float* __restrict__ fc2_w) {
    const int e = blockIdx.x;
    const int dbase = blockIdx.y * 64;
    __shared__ float lbs[RNK * HDIM];
    for (int i = threadIdx.x; i < RNK * HDIM; i += blockDim.x)
        lbs[i] = lora_B[(size_t)e * RNK * HDIM + i];
    __syncthreads();

    const int warp = threadIdx.x >> 5, lane = threadIdx.x & 31;
    for (int dd = 0; dd < 8; dd++) {
        const int d = dbase + warp * 8 + dd;
        float acc[RNK];
#pragma unroll
        for (int r = 0; r < RNK; r++) acc[r] = 0.f;
        const float* fr = fc2_w + ((size_t)e * HDIM + d) * HDIM;
        for (int o = lane; o < HDIM; o += 32) {
            float fv = fr[o];
#pragma unroll
            for (int r = 0; r < RNK; r++) acc[r] += fv * lbs[r * HDIM + o];
        }
#pragma unroll
        for (int r = 0; r < RNK; r++) {
#pragma unroll
            for (int off = 16; off > 0; off >>= 1)
                acc[r] += __shfl_xor_sync(0xffffffffu, acc[r], off);
        }
        if (lane == 0) {
#pragma unroll
            for (int r = 0; r < RNK; r++)
                g_C[(size_t)(e * RNK + r) * HDIM + d] = acc[r];
        }
    }
}

// =========================================================================
// Kernel 2: gating (fp32, exact selection math)
// =========================================================================
__global__ void gating_kernel(const float* __restrict__ x,
                              const float* __restrict__ gate_w,
                              const float* __restrict__ thr_w) {
    const int warp = threadIdx.x >> 5, lane = threadIdx.x & 31;
    const int n = blockIdx.x * 8 + warp;
    const float* xr = x + (size_t)n * HDIM;

    float a0 = 0.f, a1 = 0.f, a2 = 0.f, a3 = 0.f, at = 0.f;
    for (int k = lane; k < HDIM; k += 32) {
        float xv = xr[k];
        a0 += xv * gate_w[0 * HDIM + k];
        a1 += xv * gate_w[1 * HDIM + k];
        a2 += xv * gate_w[2 * HDIM + k];
        a3 += xv * gate_w[3 * HDIM + k];
        at += xv * thr_w[k];
    }
#pragma unroll
    for (int off = 16; off > 0; off >>= 1) {
        a0 += __shfl_xor_sync(0xffffffffu, a0, off);
        a1 += __shfl_xor_sync(0xffffffffu, a1, off);
        a2 += __shfl_xor_sync(0xffffffffu, a2, off);
        a3 += __shfl_xor_sync(0xffffffffu, a3, off);
        at += __shfl_xor_sync(0xffffffffu, at, off);
    }
    if (lane == 0) {
        float m = fmaxf(fmaxf(a0, a1), fmaxf(a2, a3));
        float e0 = expf(a0 - m), e1 = expf(a1 - m), e2 = expf(a2 - m), e3 = expf(a3 - m);
        float inv_s = 1.f / (e0 + e1 + e2 + e3);
        float thr = (1.f / (1.f + expf(-at))) * 0.25f;
        float w0 = e0 * inv_s - thr, w1 = e1 * inv_s - thr;
        float w2 = e2 * inv_s - thr, w3 = e3 * inv_s - thr;
        w0 = (w0 >= 0.f) ? w0 : 0.f;  w1 = (w1 >= 0.f) ? w1 : 0.f;
        w2 = (w2 >= 0.f) ? w2 : 0.f;  w3 = (w3 >= 0.f) ? w3 : 0.f;
        float ws = w0 + w1 + w2 + w3;
        if (ws == 0.f) ws = 1.f;
        float inv = 1.f / ws;
        g_w[n * 4 + 0] = w0 * inv;  g_w[n * 4 + 1] = w1 * inv;
        g_w[n * 4 + 2] = w2 * inv;  g_w[n * 4 + 3] = w3 * inv;
    }
}

// =========================================================================
// Kernel 3: mma.sync tf32 expert kernel.
//   Block = (expert e, 128-token tile). 512 threads = 16 warps (2m x 8n),
//   warp tile 64x32, loops 2 n-chunks of 256. K=512 in 16 chunks of 32,
//   2-stage cp.async pipeline. Epilogue: relu(H)->smem, rank-16 projection
//   into z regs; after both chunks: g_wz = w*z.
// =========================================================================
// smem layout (bytes):
//   pipeline region (aliased with Hs):
//     A0 @ 0      (128x36 f32 = 18432)
//     A1 @ 18432
//     B0 @ 36864  (256x36 f32 = 36864)
//     B1 @ 73728   ... end 110592
//   Hs  @ 0      (128x260 f32 = 133120)   [alias]
//   Ast @ 133120 (16x260 f32  = 16640)
#define EX_A(s)   ((s) * 18432)
#define EX_B(s)   (36864 + (s) * 36864)
#define EX_HS     0
#define EX_AST    133120
#define SMEM_EXP  (133120 + 16640)   // 149760 B

__device__ __forceinline__ void ex_load_tile(uint32_t smem_base, int kt, int s, int n0,
                                             const float* __restrict__ Xe,
                                             const float* __restrict__ We, int tid) {
    const uint32_t abase = smem_base + EX_A(s);
    const uint32_t bbase = smem_base + EX_B(s);
    const int koff = kt * 32;
#pragma unroll
    for (int it = 0; it < 6; it++) {
        int idx = tid + it * 512;
        if (idx < 1024) {                 // A: 128 rows x 8 x 16B
            int row = idx >> 3, c = idx & 7;
            cp16(abase + row * 144 + c * 16, Xe + (size_t)row * HDIM + koff + c * 4);
        } else {                          // B: 256 rows x 8 x 16B
            int i = idx - 1024;
            int row = i >> 3, c = i & 7;
            cp16(bbase + row * 144 + c * 16,
                 We + (size_t)(n0 + row) * HDIM + koff + c * 4);
        }
    }
}

__global__ void __launch_bounds__(512, 1)
expert_mma_kernel(const float* __restrict__ lora_A) {
    const int e    = blockIdx.x;
    const int tile = blockIdx.y;
    const int m0   = tile * 128;
    const int tid  = threadIdx.x;
    const int warp = tid >> 5, lane = tid & 31;
    const int g = lane >> 2, tg = lane & 3;
    const int warp_m = warp >> 3, warp_n = warp & 7;   // 2 x 8

    extern __shared__ char smem[];
    const uint32_t smem_base = smem_to_u32(smem);
    float* Hs  = (float*)(smem + EX_HS);    // [128][260]
    float* Ast = (float*)(smem + EX_AST);   // [16][260]

    const float* Xe = g_xr + (size_t)m0 * HDIM;
    const float* We = g_wr + (size_t)e * HDIM * HDIM;
    const float* Ae = lora_A + (size_t)e * HDIM * RNK;

    // z accumulators: thread owns (rowbase + 32q, r) for q=0..3
    const int zr = tid & 15;
    const int zrowb = tid >> 4;     // 0..31
    float zacc[4] = {0.f, 0.f, 0.f, 0.f};

    for (int nc = 0; nc < 2; nc++) {
        const int n0 = nc * 256;
        __syncthreads();   // prev Hs/Ast fully consumed

        // kick pipeline
        ex_load_tile(smem_base, 0, 0, n0, Xe, We, tid);
        asm volatile("cp.async.commit_group;" ::: "memory");
        ex_load_tile(smem_base, 1, 1, n0, Xe, We, tid);
        asm volatile("cp.async.commit_group;" ::: "memory");

        // stage lora_A chunk transposed: Ast[r][c] = A[n0+c][r]
        for (int idx = tid; idx < 256 * RNK; idx += 512) {
            int r = idx >> 8, c = idx & 255;
            Ast[r * 260 + c] = Ae[(size_t)(n0 + c) * RNK + r];
        }

        float acc[4][4][4];
#pragma unroll
        for (int mi = 0; mi < 4; mi++)
#pragma unroll
            for (int ni = 0; ni < 4; ni++)
#pragma unroll
                for (int c = 0; c < 4; c++) acc[mi][ni][c] = 0.f;

        for (int kc = 0; kc < 16; kc++) {
            const int s = kc & 1;
            if (kc < 15) asm volatile("cp.async.wait_group 1;" ::: "memory");
            else         asm volatile("cp.async.wait_group 0;" ::: "memory");
            __syncthreads();

            const uint32_t* Xs = (const uint32_t*)(smem + EX_A(s));
            const uint32_t* Ws = (const uint32_t*)(smem + EX_B(s));
#pragma unroll
            for (int st = 0; st < 4; st++) {
                const int kk = st * 8;
                uint32_t a[4][4], b[4][2];
#pragma unroll
                for (int mi = 0; mi < 4; mi++) {
                    const int row = warp_m * 64 + mi * 16 + g;
                    a[mi][0] = Xs[row * 36 + kk + tg];
                    a[mi][1] = Xs[(row + 8) * 36 + kk + tg];
                    a[mi][2] = Xs[row * 36 + kk + tg + 4];
                    a[mi][3] = Xs[(row + 8) * 36 + kk + tg + 4];
                }
#pragma unroll
                for (int ni = 0; ni < 4; ni++) {
                    const int col = warp_n * 32 + ni * 8 + g;
                    b[ni][0] = Ws[col * 36 + kk + tg];
                    b[ni][1] = Ws[col * 36 + kk + tg + 4];
                }
#pragma unroll
                for (int mi = 0; mi < 4; mi++)
#pragma unroll
                    for (int ni = 0; ni < 4; ni++)
                        mma_tf32(acc[mi][ni], a[mi], b[ni]);
            }
            __syncthreads();
            if (kc < 14) {
                ex_load_tile(smem_base, kc + 2, s, n0, Xe, We, tid);
                asm volatile("cp.async.commit_group;" ::: "memory");
            }
        }

        // stage relu(H) -> Hs  (pipeline buffers dead now)
#pragma unroll
        for (int mi = 0; mi < 4; mi++)
#pragma unroll
            for (int ni = 0; ni < 4; ni++) {
                const int row = warp_m * 64 + mi * 16 + g;
                const int col = warp_n * 32 + ni * 8 + 2 * tg;
                Hs[row * 260 + col]           = fmaxf(acc[mi][ni][0], 0.f);
                Hs[row * 260 + col + 1]       = fmaxf(acc[mi][ni][1], 0.f);
                Hs[(row + 8) * 260 + col]     = fmaxf(acc[mi][ni][2], 0.f);
                Hs[(row + 8) * 260 + col + 1] = fmaxf(acc[mi][ni][3], 0.f);
            }
        __syncthreads();

        // rank-16 projection: zacc[q] += Hs[rowb+32q][:] . Ast[zr][:]
#pragma unroll
        for (int c4 = 0; c4 < 64; c4++) {
            float4 av = *(const float4*)&Ast[zr * 260 + c4 * 4];
#pragma unroll
            for (int q = 0; q < 4; q++) {
                float4 hv = *(const float4*)&Hs[(zrowb + 32 * q) * 260 + c4 * 4];
                zacc[q] += hv.x * av.x + hv.y * av.y + hv.z * av.z + hv.w * av.w;
            }
        }
    }

    // write w*z
#pragma unroll
    for (int q = 0; q < 4; q++) {
        const int n = m0 + zrowb + 32 * q;
        const float w = g_w[n * 4 + e];
        g_wz[(size_t)n * (NEXP * RNK) + e * RNK + zr] = w * zacc[q];
    }
}

// =========================================================================
// Kernel 4: combine. out[n][dbase+d] = sum_j wz[n][j] * C[j][dbase+d]
// Grid (1024 token-tiles, 2 d-halves); 2 blocks/SM.
// =========================================================================
#define SMEM_COMBINE ((64 * 256 + 64 * 68) * 4)

__global__ void __launch_bounds__(256, 2)
combine_kernel(float* __restrict__ out) {
    extern __shared__ float csmem[];
    float* Cs = csmem;               // [64][256]
    float* Zs = Cs + 64 * 256;       // [64][68]

    const int tile = blockIdx.x;
    const int dbase = blockIdx.y * 256;
    const int tid = threadIdx.x;

    for (int i = tid; i < 64 * 64; i += 256) {     // [64][256] as float4
        int j = i >> 6, c4 = i & 63;
        ((float4*)Cs)[i] = *(const float4*)&g_C[(size_t)j * HDIM + dbase + c4 * 4];
    }
    const float* wz = g_wz + (size_t)tile * 64 * 64;
    for (int i = tid; i < 64 * 64; i += 256) {
        int row = i >> 6, j = i & 63;
        Zs[row * 68 + j] = wz[i];
    }
    __syncthreads();

    const int warp = tid >> 5, lane = tid & 31;
    const int rowbase = warp * 8;
    float* outt = out + (size_t)tile * 64 * HDIM + dbase;

    for (int rg = 0; rg < 2; rg++) {
        float acc[4][8];
#pragma unroll
        for (int rr = 0; rr < 4; rr++)
#pragma unroll
            for (int i = 0; i < 8; i++) acc[rr][i] = 0.f;

        for (int j = 0; j < 64; j++) {
            float4 c0 = *(const float4*)&Cs[j * 256 + lane * 4];
            float4 c1 = *(const float4*)&Cs[j * 256 + 128 + lane * 4];
#pragma unroll
            for (int rr = 0; rr < 4; rr++) {
                const float zv = Zs[(rowbase + rg * 4 + rr) * 68 + j];
                acc[rr][0] += zv * c0.x;  acc[rr][1] += zv * c0.y;
                acc[rr][2] += zv * c0.z;  acc[rr][3] += zv * c0.w;
                acc[rr][4] += zv * c1.x;  acc[rr][5] += zv * c1.y;
                acc[rr][6] += zv * c1.z;  acc[rr][7] += zv * c1.w;
            }
        }
#pragma unroll
        for (int rr = 0; rr < 4; rr++) {
            const int row = rowbase + rg * 4 + rr;
            *(float4*)&outt[(size_t)row * HDIM + lane * 4] =
                make_float4(acc[rr][0], acc[rr][1], acc[rr][2], acc[rr][3]);
            *(float4*)&outt[(size_t)row * HDIM + 128 + lane * 4] =
                make_float4(acc[rr][4], acc[rr][5], acc[rr][6], acc[rr][7]);
        }
    }
}

// =========================================================================
extern "C" void kernel_launch(void* const* d_in, const int* in_sizes, int n_in,
                              void* d_out, int out_size) {
    const float* x      = (const float*)d_in[0];
    const float* gate_w = (const float*)d_in[1];
    const float* thr_w  = (const float*)d_in[2];
    const float* fc1_w  = (const float*)d_in[3];
    const float* lora_A = (const float*)d_in[4];
    const float* lora_B = (const float*)d_in[5];
    const float* fc2_w  = (const float*)d_in[6];
    float* out = (float*)d_out;

    cudaFuncSetAttribute(expert_mma_kernel,
                         cudaFuncAttributeMaxDynamicSharedMemorySize, SMEM_EXP);
    cudaFuncSetAttribute(combine_kernel,
                         cudaFuncAttributeMaxDynamicSharedMemorySize, SMEM_COMBINE);

    round_x_kernel<<<(N_TOK * HDIM / 4) / 256, 256>>>((const float4*)x);
    round_w_kernel<<<(NEXP * HDIM * HDIM / 4) / 256, 256>>>((const float4*)fc1_w);
    precompute_C_kernel<<<dim3(NEXP, HDIM / 64), 256>>>(lora_B, fc2_w);
    gating_kernel<<<N_TOK / 8, 256>>>(x, gate_w, thr_w);
    expert_mma_kernel<<<dim3(NEXP, NTILES), 512, SMEM_EXP>>>(lora_A);
    combine_kernel<<<dim3(N_TOK / 64, 2), 256, SMEM_COMBINE>>>(out);
}